// round 15
// baseline (speedup 1.0000x reference)
#include <cuda_runtime.h>
#include <math.h>

#define NY 1024
#define NX 1024
#define SP 1026
#define NSTEPS 64
#define NPTS (NY*NX)
#define INV 0.02f
#define EPS 1e-10f

__device__ float g_H0[NPTS];           // boundary-row halo buffers (parity)
__device__ float g_H1[NPTS];
__device__ int g_maxDbits[NSTEPS];
__device__ unsigned g_cnt[NSTEPS];
__device__ unsigned g_done[256 * 8];

static __device__ __forceinline__ unsigned ld_acq(const unsigned* p) {
    unsigned v;
    asm volatile("ld.acquire.gpu.global.u32 %0, [%1];" : "=r"(v) : "l"(p) : "memory");
    return v;
}
static __device__ __forceinline__ void red_add_rel(unsigned* p, unsigned v) {
    asm volatile("red.release.gpu.global.add.u32 [%0], %1;" :: "l"(p), "r"(v) : "memory");
}

static __device__ __forceinline__ float smb_of(float Zs, float precip, float mask,
                                               float tma_low, float tmj_low) {
    float T_ma = tma_low - 0.0065f * Zs;
    float T_mj = tmj_low - 0.0065f * Zs;
    float acc = precip * (T_ma < 0.0f ? 1.0f : 0.0f);
    float abl = 0.5f * fmaxf(T_mj, 0.0f);
    return (acc - abl) * mask;
}

static __device__ __forceinline__ float dcalc(float h00, float h01, float h10, float h11,
                                              float z00, float z01, float z10, float z11,
                                              float CFACT) {
    float H_avg = 0.25f * (((h00 + h11) + h01) + h10);
    float sx = 0.5f * ((z01 - z00) * INV + (z11 - z10) * INV);
    float sy = 0.5f * ((z10 - z00) * INV + (z11 - z01) * INV);
    float s2 = sx * sx + sy * sy + EPS;
    float h2 = H_avg * H_avg;
    return CFACT * ((h2 * h2) * H_avg) * s2 + EPS;
}

static __device__ __forceinline__ float2 ld2(const float* p) { return *(const float2*)p; }
static __device__ __forceinline__ void st2(float* p, float2 v) { *(float2*)p = v; }

__global__ void k_reset() {
    int t = threadIdx.x;
    if (t < NSTEPS) { g_maxDbits[t] = 0; g_cnt[t] = 0u; }
    for (int k = t; k < 256 * 8; k += blockDim.x) g_done[k] = 0u;
}

// smem rows (stride SP), sized for band <= 8:
// sZt[10] | sHn[8] | sZn[8] | sDb[9] | sQ[8] | sSmb[8] | zhU | zhD = 53 rows
__global__ void __launch_bounds__(1024, 1)
k_persist(const float* __restrict__ precip,
          const float* __restrict__ tma_p,
          const float* __restrict__ tmj_p,
          const float* __restrict__ Ztopo,
          const float* __restrict__ mask,
          float* __restrict__ out) {
    extern __shared__ float sm[];
    float* sZt  = sm;                 // Ztopo rows r0-1 .. r1 (static)
    float* sHn  = sZt + 10 * SP;      // persistent own H band, rows r0..r1-1
    float* sZn  = sHn + 8 * SP;       // z = Zt + H (current), rows r0..r1-1
    float* sDb  = sZn + 8 * SP;       // D band, slot = row-(r0-1), slots 0..band
    float* sQ   = sDb + 9 * SP;       // parked dHdt rows r0..r1-1
    float* sSmb = sQ  + 8 * SP;
    float* zhU  = sSmb + 8 * SP;      // z halo row r0-1
    float* zhD  = zhU + SP;           // z halo row r1
    __shared__ unsigned wred[32];
    __shared__ float sdt[1];

    const int t  = threadIdx.x;
    const int ct = t & 511;
    const int rg = t >> 9;
    const int c0 = ct * 2;
    const int lane = t & 31, wid = t >> 5;
    const int nb = gridDim.x, bid = blockIdx.x;
    const int cl = (c0 == 0) ? 0 : c0 - 1;
    const unsigned FULL = 0xFFFFFFFFu;

    int base = NY / nb, rem = NY % nb;
    const int r0 = bid * base + (bid < rem ? bid : rem);
    const int r1 = r0 + base + (bid < rem ? 1 : 0);
    const int band = r1 - r0;                  // <= 8 (buffers sized for 8)

    const int splitA = (band + 1) >> 1;
    const int a_lo = rg ? splitA : 0;          // own H/dHdt rows (band-local)
    const int a_hi = rg ? band : splitA;
    const int nB = band - 1;
    const int splitB = (nB + 1) >> 1;
    const int bI_lo = rg ? splitB : 0;         // interior D rows
    const int bI_hi = rg ? nB : splitB;

    const float tma = tma_p[0], tmj = tmj_p[0];
    const float CFACT = (float)(1e-17 * 8927.1 * 8927.1 * 8927.1);
    const bool p0in = (ct > 0);
    const bool p1in = (ct < 511);

    // ---- one-time init ----
    if (t < 53) { sm[t * SP + 1024] = 0.f; sm[t * SP + 1025] = 0.f; }
    for (int sl = rg; sl <= band + 1; sl += 2) {
        int row = r0 - 1 + sl;
        float2 zt = make_float2(0.f, 0.f);
        if (row >= 0 && row < NY) zt = ld2(Ztopo + row * NX + c0);
        st2(sZt + sl * SP + c0, zt);
    }
    __syncthreads();
    for (int jb = rg; jb < band; jb += 2) {
        int j = r0 + jb;
        st2(sHn + jb * SP + c0, make_float2(0.f, 0.f));
        float2 zt = ld2(sZt + (jb + 1) * SP + c0);
        st2(sZn + jb * SP + c0, zt);               // z = Zt (H = 0)
        float2 pr = ld2(precip + j * NX + c0);
        float2 mk = ld2(mask + j * NX + c0);
        st2(sSmb + jb * SP + c0,
            make_float2(smb_of(zt.x, pr.x, mk.x, tma, tmj),
                        smb_of(zt.y, pr.y, mk.y, tma, tmj)));
    }
    if (rg == 0) {
        #pragma unroll
        for (int k = 0; k < 9; k++) st2(sDb + k * SP + c0, make_float2(EPS, EPS));
        st2(zhU + c0, ld2(sZt + c0));                   // z(r0-1) at step 0 (H=0)
    } else {
        st2(zhD + c0, ld2(sZt + (band + 1) * SP + c0)); // z(r1) at step 0
    }
    __syncthreads();

    float dt = 0.5f;                 // maxD_0 = EPS -> dt_0 = DTMAX
    float time = 0.0f, tlast = 0.0f;

    // ---- prologue: dHdt_0 (H=0, D=EPS) ----
    for (int jb = a_lo; jb < a_hi; jb++) {
        float2 zu = (jb == 0) ? ld2(zhU + c0) : ld2(sZn + (jb - 1) * SP + c0);
        float2 zc = ld2(sZn + jb * SP + c0);
        float zl = sZn[jb * SP + cl];
        float zr = sZn[jb * SP + c0 + 2];
        float2 zd = (jb == band - 1) ? ld2(zhD + c0) : ld2(sZn + (jb + 1) * SP + c0);
        float2 Dup = ld2(sDb + jb * SP + c0); float Dup_l = sDb[jb * SP + cl];
        float2 Dcu = ld2(sDb + (jb + 1) * SP + c0); float Dcu_l = sDb[(jb + 1) * SP + cl];
        float qxr0 = -(0.5f * (Dup.x + Dcu.x)) * (zc.y - zc.x) * INV;
        float qxl0 = -(0.5f * (Dup_l + Dcu_l)) * (zc.x - zl) * INV;
        float qyd0 = -(0.5f * (Dcu_l + Dcu.x)) * (zd.x - zc.x) * INV;
        float qyu0 = -(0.5f * (Dup_l + Dup.x)) * (zc.x - zu.x) * INV;
        float q0 = -((qxr0 - qxl0) * INV + (qyd0 - qyu0) * INV);
        float qxr1 = -(0.5f * (Dup.y + Dcu.y)) * (zr - zc.y) * INV;
        float qxl1 = -(0.5f * (Dup.x + Dcu.x)) * (zc.y - zc.x) * INV;
        float qyd1 = -(0.5f * (Dcu.x + Dcu.y)) * (zd.y - zc.y) * INV;
        float qyu1 = -(0.5f * (Dup.x + Dup.y)) * (zc.y - zu.y) * INV;
        float q1 = -((qxr1 - qxl1) * INV + (qyd1 - qyu1) * INV);
        st2(sQ + jb * SP + c0, make_float2(q0, q1));
    }
    __syncthreads();

    for (int s = 0; s < NSTEPS; s++) {
        float tnew = time + dt;
        bool  upd  = (tnew - tlast) >= 5.0f;
        const bool last = (s == NSTEPS - 1);
        float* HB = ((s + 1) & 1) ? g_H1 : g_H0;   // H_{s+1} boundary buffer

        // ---- A: apply dt_s, stage Hn and Zn ----
        for (int jb = a_lo; jb < a_hi; jb++) {
            int j = r0 + jb;
            float2 h2  = ld2(sHn + jb * SP + c0);
            float2 q2  = ld2(sQ + jb * SP + c0);
            float2 sb2 = ld2(sSmb + jb * SP + c0);
            float2 zt2 = ld2(sZt + (jb + 1) * SP + c0);
            bool jIn = (j > 0) && (j < NY - 1);
            float Hn0 = (jIn && p0in) ? fmaxf(h2.x + dt * (q2.x + sb2.x), 0.f) : h2.x;
            float Hn1 = (jIn && p1in) ? fmaxf(h2.y + dt * (q2.y + sb2.y), 0.f) : h2.y;
            float2 Hn2 = make_float2(Hn0, Hn1);
            float Zn0 = zt2.x + Hn0, Zn1 = zt2.y + Hn1;
            st2(sHn + jb * SP + c0, Hn2);
            st2(sZn + jb * SP + c0, make_float2(Zn0, Zn1));
            if (jb == 0 || jb == band - 1) st2(HB + j * NX + c0, Hn2);
            if (last) st2(out + j * NX + c0, Hn2);
            if (upd) {
                float2 pr = ld2(precip + j * NX + c0);
                float2 mk = ld2(mask + j * NX + c0);
                st2(sSmb + jb * SP + c0,
                    make_float2(smb_of(Zn0, pr.x, mk.x, tma, tmj),
                                smb_of(Zn1, pr.y, mk.y, tma, tmj)));
            }
        }
        time = tnew;
        if (upd) tlast = tnew;
        __syncthreads();
        if (last) break;
        if (t == 0) red_add_rel(&g_done[bid * 8], 1u);     // publish H_{s+1} boundary rows

        // ---- B: D_{s+1} interior (rolled, shfl for right scalars) ----
        float lmax = 0.f;
        if (bI_lo < bI_hi) {
            float2 ha = ld2(sHn + bI_lo * SP + c0);
            float2 za = ld2(sZn + bI_lo * SP + c0);
            float haR = __shfl_down_sync(FULL, ha.x, 1);
            float zaR = __shfl_down_sync(FULL, za.x, 1);
            if (lane == 31) { haR = sHn[bI_lo * SP + c0 + 2]; zaR = sZn[bI_lo * SP + c0 + 2]; }
            for (int jb = bI_lo; jb < bI_hi; jb++) {
                float2 hb = ld2(sHn + (jb + 1) * SP + c0);
                float2 zb = ld2(sZn + (jb + 1) * SP + c0);
                float hbR = __shfl_down_sync(FULL, hb.x, 1);
                float zbR = __shfl_down_sync(FULL, zb.x, 1);
                if (lane == 31) { hbR = sHn[(jb + 1) * SP + c0 + 2]; zbR = sZn[(jb + 1) * SP + c0 + 2]; }
                float D0 = dcalc(ha.x, ha.y, hb.x, hb.y, za.x, za.y, zb.x, zb.y, CFACT);
                float D1 = dcalc(ha.y, haR, hb.y, hbR, za.y, zaR, zb.y, zbR, CFACT);
                st2(sDb + (jb + 1) * SP + c0, make_float2(D0, D1));
                lmax = fmaxf(lmax, D0);
                if (p1in) lmax = fmaxf(lmax, D1);
                ha = hb; haR = hbR; za = zb; zaR = zbR;
            }
        }

        // wait neighbor H_{s+1} flags
        if (t == 0 && bid > 0)       { while (ld_acq(&g_done[(bid - 1) * 8]) < (unsigned)(s + 1)) __nanosleep(20); }
        if (t == 32 && bid < nb - 1) { while (ld_acq(&g_done[(bid + 1) * 8]) < (unsigned)(s + 1)) __nanosleep(20); }
        __syncthreads();

        // ---- boundary D rows + z halo staging ----
        if (rg == 0) {
            if (r0 >= 1) {
                const float* pa = HB + (r0 - 1) * NX + c0;
                float2 ha = __ldcg((const float2*)pa);
                float  haR = p1in ? __ldcg(pa + 2) : 0.f;
                float2 zta = ld2(sZt + c0); float ztaR = sZt[c0 + 2];
                float2 za = make_float2(zta.x + ha.x, zta.y + ha.y); float zaR = ztaR + haR;
                st2(zhU + c0, za);
                float2 hb = ld2(sHn + c0); float hbR = sHn[c0 + 2];
                float2 zb = ld2(sZn + c0); float zbR = sZn[c0 + 2];
                float D0 = dcalc(ha.x, ha.y, hb.x, hb.y, za.x, za.y, zb.x, zb.y, CFACT);
                float D1 = dcalc(ha.y, haR, hb.y, hbR, za.y, zaR, zb.y, zbR, CFACT);
                st2(sDb + c0, make_float2(D0, D1));
                lmax = fmaxf(lmax, D0);
                if (p1in) lmax = fmaxf(lmax, D1);
            }
        } else {
            if (r1 <= NY - 1) {
                float2 ha = ld2(sHn + (band - 1) * SP + c0); float haR = sHn[(band - 1) * SP + c0 + 2];
                float2 za = ld2(sZn + (band - 1) * SP + c0); float zaR = sZn[(band - 1) * SP + c0 + 2];
                const float* pb = HB + r1 * NX + c0;
                float2 hb = __ldcg((const float2*)pb);
                float  hbR = p1in ? __ldcg(pb + 2) : 0.f;
                float2 ztb = ld2(sZt + (band + 1) * SP + c0); float ztbR = sZt[(band + 1) * SP + c0 + 2];
                float2 zb = make_float2(ztb.x + hb.x, ztb.y + hb.y); float zbR = ztbR + hbR;
                st2(zhD + c0, zb);
                float D0 = dcalc(ha.x, ha.y, hb.x, hb.y, za.x, za.y, zb.x, zb.y, CFACT);
                float D1 = dcalc(ha.y, haR, hb.y, hbR, za.y, zaR, zb.y, zbR, CFACT);
                st2(sDb + band * SP + c0, make_float2(D0, D1));
                lmax = fmaxf(lmax, D0);
                if (p1in) lmax = fmaxf(lmax, D1);
            }
        }

        // ---- block max -> atomicMax slot s+1 + arrive counter (early) ----
        unsigned lb = __reduce_max_sync(FULL, __float_as_uint(lmax));
        if (lane == 0) wred[wid] = lb;
        __syncthreads();
        if (wid == 0) {
            unsigned m = __reduce_max_sync(FULL, wred[lane]);
            if (lane == 0) {
                atomicMax(&g_maxDbits[s + 1], (int)m);
                red_add_rel(&g_cnt[s + 1], 1u);
            }
        }

        // ---- C: dHdt_{s+1} (rolled + shfl) — overlaps global max propagation ----
        {
            float2 zu = (a_lo == 0) ? ld2(zhU + c0) : ld2(sZn + (a_lo - 1) * SP + c0);
            float2 zc = ld2(sZn + a_lo * SP + c0);
            float2 Dup = ld2(sDb + a_lo * SP + c0);
            float Dup_l = __shfl_up_sync(FULL, Dup.y, 1);
            if (lane == 0) Dup_l = sDb[a_lo * SP + cl];
            for (int jb = a_lo; jb < a_hi; jb++) {
                float2 zd = (jb == band - 1) ? ld2(zhD + c0) : ld2(sZn + (jb + 1) * SP + c0);
                float zl = __shfl_up_sync(FULL, zc.y, 1);
                float zr = __shfl_down_sync(FULL, zc.x, 1);
                if (lane == 0)  zl = sZn[jb * SP + cl];
                if (lane == 31) zr = sZn[jb * SP + c0 + 2];
                float2 Dcu = ld2(sDb + (jb + 1) * SP + c0);
                float Dcu_l = __shfl_up_sync(FULL, Dcu.y, 1);
                if (lane == 0) Dcu_l = sDb[(jb + 1) * SP + cl];
                float qxr0 = -(0.5f * (Dup.x + Dcu.x)) * (zc.y - zc.x) * INV;
                float qxl0 = -(0.5f * (Dup_l + Dcu_l)) * (zc.x - zl) * INV;
                float qyd0 = -(0.5f * (Dcu_l + Dcu.x)) * (zd.x - zc.x) * INV;
                float qyu0 = -(0.5f * (Dup_l + Dup.x)) * (zc.x - zu.x) * INV;
                float q0 = -((qxr0 - qxl0) * INV + (qyd0 - qyu0) * INV);
                float qxr1 = -(0.5f * (Dup.y + Dcu.y)) * (zr - zc.y) * INV;
                float qxl1 = -(0.5f * (Dup.x + Dcu.x)) * (zc.y - zc.x) * INV;
                float qyd1 = -(0.5f * (Dcu.x + Dcu.y)) * (zd.y - zc.y) * INV;
                float qyu1 = -(0.5f * (Dup.x + Dup.y)) * (zc.y - zu.y) * INV;
                float q1 = -((qxr1 - qxl1) * INV + (qyd1 - qyu1) * INV);
                st2(sQ + jb * SP + c0, make_float2(q0, q1));
                zu = zc; zc = zd; Dup = Dcu; Dup_l = Dcu_l;
            }
        }
        __syncthreads();

        // ---- D: fetch dt_{s+1} ----
        if (t == 0) {
            while (ld_acq(&g_cnt[s + 1]) < (unsigned)nb) __nanosleep(20);
            sdt[0] = __int_as_float(__ldcg(&g_maxDbits[s + 1]));
        }
        __syncthreads();
        float maxD = sdt[0];
        dt = fminf(2500.0f / (2.7f * maxD), 0.5f);
        if (!(time < 32.0f)) dt = 0.0f;
    }
}

extern "C" void kernel_launch(void* const* d_in, const int* in_sizes, int n_in,
                              void* d_out, int out_size) {
    const float* precip = (const float*)d_in[0];
    const float* tma_p  = (const float*)d_in[1];
    const float* tmj_p  = (const float*)d_in[2];
    const float* Ztopo  = (const float*)d_in[3];
    const float* mask   = (const float*)d_in[4];
    float* out = (float*)d_out;

    int dev = 0;
    cudaGetDevice(&dev);
    int sms = 0;
    cudaDeviceGetAttribute(&sms, cudaDevAttrMultiProcessorCount, dev);
    if (sms < 1) sms = 1;
    if (sms > 256) sms = 256;
    if (sms < 128) sms = 128;   // keep band <= 8 (smem sized for 8)

    const int smem_bytes = 53 * SP * (int)sizeof(float);
    cudaFuncSetAttribute(k_persist, cudaFuncAttributeMaxDynamicSharedMemorySize, smem_bytes);

    k_reset<<<1, 1024>>>();
    k_persist<<<sms, 1024, smem_bytes>>>(precip, tma_p, tmj_p, Ztopo, mask, out);
}

// round 16
// speedup vs baseline: 1.0680x; 1.0680x over previous
#include <cuda_runtime.h>
#include <math.h>

#define NY 1024
#define NX 1024
#define SP 1026
#define NSTEPS 64
#define NPTS (NY*NX)
#define INV 0.02f
#define EPS 1e-10f

__device__ float g_H0[NPTS];           // boundary-row halo buffers (parity)
__device__ float g_H1[NPTS];
__device__ int g_maxDbits[NSTEPS];
__device__ unsigned g_cnt[NSTEPS];
__device__ unsigned g_done[256 * 8];

static __device__ __forceinline__ unsigned ld_acq(const unsigned* p) {
    unsigned v;
    asm volatile("ld.acquire.gpu.global.u32 %0, [%1];" : "=r"(v) : "l"(p) : "memory");
    return v;
}
static __device__ __forceinline__ void red_add_rel(unsigned* p, unsigned v) {
    asm volatile("red.release.gpu.global.add.u32 [%0], %1;" :: "l"(p), "r"(v) : "memory");
}

static __device__ __forceinline__ float smb_of(float Zs, float precip, float mask,
                                               float tma_low, float tmj_low) {
    float T_ma = tma_low - 0.0065f * Zs;
    float T_mj = tmj_low - 0.0065f * Zs;
    float acc = precip * (T_ma < 0.0f ? 1.0f : 0.0f);
    float abl = 0.5f * fmaxf(T_mj, 0.0f);
    return (acc - abl) * mask;
}

static __device__ __forceinline__ float dcalc(float h00, float h01, float h10, float h11,
                                              float z00, float z01, float z10, float z11,
                                              float CFACT) {
    float H_avg = 0.25f * (((h00 + h11) + h01) + h10);
    float sx = 0.5f * ((z01 - z00) * INV + (z11 - z10) * INV);
    float sy = 0.5f * ((z10 - z00) * INV + (z11 - z01) * INV);
    float s2 = sx * sx + sy * sy + EPS;
    float h2 = H_avg * H_avg;
    return CFACT * ((h2 * h2) * H_avg) * s2 + EPS;
}

static __device__ __forceinline__ float2 ld2(const float* p) { return *(const float2*)p; }
static __device__ __forceinline__ void st2(float* p, float2 v) { *(float2*)p = v; }

__global__ void k_reset() {
    int t = threadIdx.x;
    if (t < NSTEPS) { g_maxDbits[t] = 0; g_cnt[t] = 0u; }
    for (int k = t; k < 256 * 8; k += blockDim.x) g_done[k] = 0u;
}

// smem rows (stride SP), sized for band <= 8:
// sZt[10] | sHn[8] | sZn[8] | sDb[9] | sQ[8] | sSmb[8] | zhU | zhD = 53 rows
__global__ void __launch_bounds__(1024, 1)
k_persist(const float* __restrict__ precip,
          const float* __restrict__ tma_p,
          const float* __restrict__ tmj_p,
          const float* __restrict__ Ztopo,
          const float* __restrict__ mask,
          float* __restrict__ out) {
    extern __shared__ float sm[];
    float* sZt  = sm;                 // Ztopo rows r0-1 .. r1 (static)
    float* sHn  = sZt + 10 * SP;      // persistent own H band, rows r0..r1-1
    float* sZn  = sHn + 8 * SP;       // z = Zt + H (current), rows r0..r1-1
    float* sDb  = sZn + 8 * SP;       // D band, slot = row-(r0-1), slots 0..band
    float* sQ   = sDb + 9 * SP;       // parked dHdt rows r0..r1-1
    float* sSmb = sQ  + 8 * SP;
    float* zhU  = sSmb + 8 * SP;      // z halo row r0-1
    float* zhD  = zhU + SP;           // z halo row r1
    __shared__ unsigned wred[32];
    __shared__ float sdt[1];

    const int t  = threadIdx.x;
    const int ct = t & 511;
    const int rg = t >> 9;
    const int c0 = ct * 2;
    const int lane = t & 31, wid = t >> 5;
    const int nb = gridDim.x, bid = blockIdx.x;
    const int cl = (c0 == 0) ? 0 : c0 - 1;
    const unsigned FULL = 0xFFFFFFFFu;

    int base = NY / nb, rem = NY % nb;
    const int r0 = bid * base + (bid < rem ? bid : rem);
    const int r1 = r0 + base + (bid < rem ? 1 : 0);
    const int band = r1 - r0;                  // <= 8 (buffers sized for 8)

    const int splitA = (band + 1) >> 1;
    const int a_lo = rg ? splitA : 0;          // own H/dHdt rows (band-local)
    const int a_hi = rg ? band : splitA;
    const int nB = band - 1;
    const int splitB = (nB + 1) >> 1;
    const int bI_lo = rg ? splitB : 0;         // interior D rows
    const int bI_hi = rg ? nB : splitB;

    const float tma = tma_p[0], tmj = tmj_p[0];
    const float CFACT = (float)(1e-17 * 8927.1 * 8927.1 * 8927.1);
    const bool p0in = (ct > 0);
    const bool p1in = (ct < 511);

    // ---- one-time init ----
    if (t < 53) { sm[t * SP + 1024] = 0.f; sm[t * SP + 1025] = 0.f; }
    for (int sl = rg; sl <= band + 1; sl += 2) {
        int row = r0 - 1 + sl;
        float2 zt = make_float2(0.f, 0.f);
        if (row >= 0 && row < NY) zt = ld2(Ztopo + row * NX + c0);
        st2(sZt + sl * SP + c0, zt);
    }
    __syncthreads();
    for (int jb = rg; jb < band; jb += 2) {
        int j = r0 + jb;
        st2(sHn + jb * SP + c0, make_float2(0.f, 0.f));
        float2 zt = ld2(sZt + (jb + 1) * SP + c0);
        st2(sZn + jb * SP + c0, zt);               // z = Zt (H = 0)
        float2 pr = ld2(precip + j * NX + c0);
        float2 mk = ld2(mask + j * NX + c0);
        st2(sSmb + jb * SP + c0,
            make_float2(smb_of(zt.x, pr.x, mk.x, tma, tmj),
                        smb_of(zt.y, pr.y, mk.y, tma, tmj)));
    }
    if (rg == 0) {
        #pragma unroll
        for (int k = 0; k < 9; k++) st2(sDb + k * SP + c0, make_float2(EPS, EPS));
        st2(zhU + c0, ld2(sZt + c0));                   // z(r0-1) at step 0 (H=0)
    } else {
        st2(zhD + c0, ld2(sZt + (band + 1) * SP + c0)); // z(r1) at step 0
    }
    __syncthreads();

    float dt = 0.5f;                 // maxD_0 = EPS -> dt_0 = DTMAX
    float time = 0.0f, tlast = 0.0f;

    // ---- prologue: dHdt_0 (H=0, D=EPS), rolled ----
    {
        float2 zu = (a_lo == 0) ? ld2(zhU + c0) : ld2(sZn + (a_lo - 1) * SP + c0);
        float2 zc = ld2(sZn + a_lo * SP + c0);
        float2 Dup = ld2(sDb + a_lo * SP + c0);
        float Dup_l = sDb[a_lo * SP + cl];
        for (int jb = a_lo; jb < a_hi; jb++) {
            float2 zd = (jb == band - 1) ? ld2(zhD + c0) : ld2(sZn + (jb + 1) * SP + c0);
            float zl = sZn[jb * SP + cl];
            float zr = sZn[jb * SP + c0 + 2];
            float2 Dcu = ld2(sDb + (jb + 1) * SP + c0);
            float Dcu_l = sDb[(jb + 1) * SP + cl];
            float qxr0 = -(0.5f * (Dup.x + Dcu.x)) * (zc.y - zc.x) * INV;
            float qxl0 = -(0.5f * (Dup_l + Dcu_l)) * (zc.x - zl) * INV;
            float qyd0 = -(0.5f * (Dcu_l + Dcu.x)) * (zd.x - zc.x) * INV;
            float qyu0 = -(0.5f * (Dup_l + Dup.x)) * (zc.x - zu.x) * INV;
            float q0 = -((qxr0 - qxl0) * INV + (qyd0 - qyu0) * INV);
            float qxr1 = -(0.5f * (Dup.y + Dcu.y)) * (zr - zc.y) * INV;
            float qxl1 = -(0.5f * (Dup.x + Dcu.x)) * (zc.y - zc.x) * INV;
            float qyd1 = -(0.5f * (Dcu.x + Dcu.y)) * (zd.y - zc.y) * INV;
            float qyu1 = -(0.5f * (Dup.x + Dup.y)) * (zc.y - zu.y) * INV;
            float q1 = -((qxr1 - qxl1) * INV + (qyd1 - qyu1) * INV);
            st2(sQ + jb * SP + c0, make_float2(q0, q1));
            zu = zc; zc = zd; Dup = Dcu; Dup_l = Dcu_l;
        }
    }
    __syncthreads();

    for (int s = 0; s < NSTEPS; s++) {
        float tnew = time + dt;
        bool  upd  = (tnew - tlast) >= 5.0f;
        const bool last = (s == NSTEPS - 1);
        float* HB = ((s + 1) & 1) ? g_H1 : g_H0;   // H_{s+1} boundary buffer

        // ---- A: apply dt_s, stage Hn and Zn ----
        for (int jb = a_lo; jb < a_hi; jb++) {
            int j = r0 + jb;
            float2 h2  = ld2(sHn + jb * SP + c0);
            float2 q2  = ld2(sQ + jb * SP + c0);
            float2 sb2 = ld2(sSmb + jb * SP + c0);
            float2 zt2 = ld2(sZt + (jb + 1) * SP + c0);
            bool jIn = (j > 0) && (j < NY - 1);
            float Hn0 = (jIn && p0in) ? fmaxf(h2.x + dt * (q2.x + sb2.x), 0.f) : h2.x;
            float Hn1 = (jIn && p1in) ? fmaxf(h2.y + dt * (q2.y + sb2.y), 0.f) : h2.y;
            float2 Hn2 = make_float2(Hn0, Hn1);
            float Zn0 = zt2.x + Hn0, Zn1 = zt2.y + Hn1;
            st2(sHn + jb * SP + c0, Hn2);
            st2(sZn + jb * SP + c0, make_float2(Zn0, Zn1));
            if (jb == 0 || jb == band - 1) st2(HB + j * NX + c0, Hn2);
            if (last) st2(out + j * NX + c0, Hn2);
            if (upd) {
                float2 pr = ld2(precip + j * NX + c0);
                float2 mk = ld2(mask + j * NX + c0);
                st2(sSmb + jb * SP + c0,
                    make_float2(smb_of(Zn0, pr.x, mk.x, tma, tmj),
                                smb_of(Zn1, pr.y, mk.y, tma, tmj)));
            }
        }
        time = tnew;
        if (upd) tlast = tnew;
        __syncthreads();
        if (last) break;
        if (t == 0) red_add_rel(&g_done[bid * 8], 1u);     // publish H_{s+1} boundary rows

        // ---- B: D_{s+1} interior (rolled, scalar LDS for right neighbors) ----
        float lmax = 0.f;
        if (bI_lo < bI_hi) {
            float2 ha = ld2(sHn + bI_lo * SP + c0); float haR = sHn[bI_lo * SP + c0 + 2];
            float2 za = ld2(sZn + bI_lo * SP + c0); float zaR = sZn[bI_lo * SP + c0 + 2];
            for (int jb = bI_lo; jb < bI_hi; jb++) {
                float2 hb = ld2(sHn + (jb + 1) * SP + c0); float hbR = sHn[(jb + 1) * SP + c0 + 2];
                float2 zb = ld2(sZn + (jb + 1) * SP + c0); float zbR = sZn[(jb + 1) * SP + c0 + 2];
                float D0 = dcalc(ha.x, ha.y, hb.x, hb.y, za.x, za.y, zb.x, zb.y, CFACT);
                float D1 = dcalc(ha.y, haR, hb.y, hbR, za.y, zaR, zb.y, zbR, CFACT);
                st2(sDb + (jb + 1) * SP + c0, make_float2(D0, D1));
                lmax = fmaxf(lmax, D0);
                if (p1in) lmax = fmaxf(lmax, D1);
                ha = hb; haR = hbR; za = zb; zaR = zbR;
            }
        }

        // wait neighbor H_{s+1} flags
        if (t == 0 && bid > 0)       { while (ld_acq(&g_done[(bid - 1) * 8]) < (unsigned)(s + 1)) __nanosleep(20); }
        if (t == 32 && bid < nb - 1) { while (ld_acq(&g_done[(bid + 1) * 8]) < (unsigned)(s + 1)) __nanosleep(20); }
        __syncthreads();

        // ---- boundary D rows + z halo staging ----
        if (rg == 0) {
            if (r0 >= 1) {
                const float* pa = HB + (r0 - 1) * NX + c0;
                float2 ha = __ldcg((const float2*)pa);
                float  haR = p1in ? __ldcg(pa + 2) : 0.f;
                float2 zta = ld2(sZt + c0); float ztaR = sZt[c0 + 2];
                float2 za = make_float2(zta.x + ha.x, zta.y + ha.y); float zaR = ztaR + haR;
                st2(zhU + c0, za);
                float2 hb = ld2(sHn + c0); float hbR = sHn[c0 + 2];
                float2 zb = ld2(sZn + c0); float zbR = sZn[c0 + 2];
                float D0 = dcalc(ha.x, ha.y, hb.x, hb.y, za.x, za.y, zb.x, zb.y, CFACT);
                float D1 = dcalc(ha.y, haR, hb.y, hbR, za.y, zaR, zb.y, zbR, CFACT);
                st2(sDb + c0, make_float2(D0, D1));
                lmax = fmaxf(lmax, D0);
                if (p1in) lmax = fmaxf(lmax, D1);
            }
        } else {
            if (r1 <= NY - 1) {
                float2 ha = ld2(sHn + (band - 1) * SP + c0); float haR = sHn[(band - 1) * SP + c0 + 2];
                float2 za = ld2(sZn + (band - 1) * SP + c0); float zaR = sZn[(band - 1) * SP + c0 + 2];
                const float* pb = HB + r1 * NX + c0;
                float2 hb = __ldcg((const float2*)pb);
                float  hbR = p1in ? __ldcg(pb + 2) : 0.f;
                float2 ztb = ld2(sZt + (band + 1) * SP + c0); float ztbR = sZt[(band + 1) * SP + c0 + 2];
                float2 zb = make_float2(ztb.x + hb.x, ztb.y + hb.y); float zbR = ztbR + hbR;
                st2(zhD + c0, zb);
                float D0 = dcalc(ha.x, ha.y, hb.x, hb.y, za.x, za.y, zb.x, zb.y, CFACT);
                float D1 = dcalc(ha.y, haR, hb.y, hbR, za.y, zaR, zb.y, zbR, CFACT);
                st2(sDb + band * SP + c0, make_float2(D0, D1));
                lmax = fmaxf(lmax, D0);
                if (p1in) lmax = fmaxf(lmax, D1);
            }
        }

        // ---- block max -> atomicMax slot s+1 + arrive counter (early) ----
        unsigned lb = __reduce_max_sync(FULL, __float_as_uint(lmax));
        if (lane == 0) wred[wid] = lb;
        __syncthreads();
        if (wid == 0) {
            unsigned m = __reduce_max_sync(FULL, wred[lane]);
            if (lane == 0) {
                atomicMax(&g_maxDbits[s + 1], (int)m);
                red_add_rel(&g_cnt[s + 1], 1u);
            }
        }

        // ---- C: dHdt_{s+1} (rolled, scalar LDS laterals) — overlaps max propagation ----
        {
            float2 zu = (a_lo == 0) ? ld2(zhU + c0) : ld2(sZn + (a_lo - 1) * SP + c0);
            float2 zc = ld2(sZn + a_lo * SP + c0);
            float2 Dup = ld2(sDb + a_lo * SP + c0);
            float Dup_l = sDb[a_lo * SP + cl];
            for (int jb = a_lo; jb < a_hi; jb++) {
                float2 zd = (jb == band - 1) ? ld2(zhD + c0) : ld2(sZn + (jb + 1) * SP + c0);
                float zl = sZn[jb * SP + cl];
                float zr = sZn[jb * SP + c0 + 2];
                float2 Dcu = ld2(sDb + (jb + 1) * SP + c0);
                float Dcu_l = sDb[(jb + 1) * SP + cl];
                float qxr0 = -(0.5f * (Dup.x + Dcu.x)) * (zc.y - zc.x) * INV;
                float qxl0 = -(0.5f * (Dup_l + Dcu_l)) * (zc.x - zl) * INV;
                float qyd0 = -(0.5f * (Dcu_l + Dcu.x)) * (zd.x - zc.x) * INV;
                float qyu0 = -(0.5f * (Dup_l + Dup.x)) * (zc.x - zu.x) * INV;
                float q0 = -((qxr0 - qxl0) * INV + (qyd0 - qyu0) * INV);
                float qxr1 = -(0.5f * (Dup.y + Dcu.y)) * (zr - zc.y) * INV;
                float qxl1 = -(0.5f * (Dup.x + Dcu.x)) * (zc.y - zc.x) * INV;
                float qyd1 = -(0.5f * (Dcu.x + Dcu.y)) * (zd.y - zc.y) * INV;
                float qyu1 = -(0.5f * (Dup.x + Dup.y)) * (zc.y - zu.y) * INV;
                float q1 = -((qxr1 - qxl1) * INV + (qyd1 - qyu1) * INV);
                st2(sQ + jb * SP + c0, make_float2(q0, q1));
                zu = zc; zc = zd; Dup = Dcu; Dup_l = Dcu_l;
            }
        }
        __syncthreads();

        // ---- D: fetch dt_{s+1} ----
        if (t == 0) {
            while (ld_acq(&g_cnt[s + 1]) < (unsigned)nb) __nanosleep(20);
            sdt[0] = __int_as_float(__ldcg(&g_maxDbits[s + 1]));
        }
        __syncthreads();
        float maxD = sdt[0];
        dt = fminf(2500.0f / (2.7f * maxD), 0.5f);
        if (!(time < 32.0f)) dt = 0.0f;
    }
}

extern "C" void kernel_launch(void* const* d_in, const int* in_sizes, int n_in,
                              void* d_out, int out_size) {
    const float* precip = (const float*)d_in[0];
    const float* tma_p  = (const float*)d_in[1];
    const float* tmj_p  = (const float*)d_in[2];
    const float* Ztopo  = (const float*)d_in[3];
    const float* mask   = (const float*)d_in[4];
    float* out = (float*)d_out;

    int dev = 0;
    cudaGetDevice(&dev);
    int sms = 0;
    cudaDeviceGetAttribute(&sms, cudaDevAttrMultiProcessorCount, dev);
    if (sms < 1) sms = 1;
    if (sms > 256) sms = 256;
    if (sms < 128) sms = 128;   // keep band <= 8 (smem sized for 8)

    const int smem_bytes = 53 * SP * (int)sizeof(float);
    cudaFuncSetAttribute(k_persist, cudaFuncAttributeMaxDynamicSharedMemorySize, smem_bytes);

    k_reset<<<1, 1024>>>();
    k_persist<<<sms, 1024, smem_bytes>>>(precip, tma_p, tmj_p, Ztopo, mask, out);
}

// round 17
// speedup vs baseline: 1.0843x; 1.0153x over previous
#include <cuda_runtime.h>
#include <math.h>

#define NY 1024
#define NX 1024
#define SP 1026
#define NSTEPS 64
#define NPTS (NY*NX)
#define INV 0.02f
#define EPS 1e-10f

__device__ float g_H0[NPTS];           // boundary-row halo buffers (parity)
__device__ float g_H1[NPTS];
__device__ int g_maxDbits[NSTEPS];
__device__ unsigned g_cnt[NSTEPS];
__device__ unsigned g_done[256 * 8];

static __device__ __forceinline__ unsigned ld_acq(const unsigned* p) {
    unsigned v;
    asm volatile("ld.acquire.gpu.global.u32 %0, [%1];" : "=r"(v) : "l"(p) : "memory");
    return v;
}
static __device__ __forceinline__ void red_add_rel(unsigned* p, unsigned v) {
    asm volatile("red.release.gpu.global.add.u32 [%0], %1;" :: "l"(p), "r"(v) : "memory");
}

static __device__ __forceinline__ float smb_of(float Zs, float precip, float mask,
                                               float tma_low, float tmj_low) {
    float T_ma = tma_low - 0.0065f * Zs;
    float T_mj = tmj_low - 0.0065f * Zs;
    float acc = precip * (T_ma < 0.0f ? 1.0f : 0.0f);
    float abl = 0.5f * fmaxf(T_mj, 0.0f);
    return (acc - abl) * mask;
}

static __device__ __forceinline__ float dcalc(float h00, float h01, float h10, float h11,
                                              float z00, float z01, float z10, float z11,
                                              float CFACT) {
    float H_avg = 0.25f * (((h00 + h11) + h01) + h10);
    float sx = 0.5f * ((z01 - z00) * INV + (z11 - z10) * INV);
    float sy = 0.5f * ((z10 - z00) * INV + (z11 - z01) * INV);
    float s2 = sx * sx + sy * sy + EPS;
    float h2 = H_avg * H_avg;
    return CFACT * ((h2 * h2) * H_avg) * s2 + EPS;
}

static __device__ __forceinline__ float2 ld2(const float* p) { return *(const float2*)p; }
static __device__ __forceinline__ void st2(float* p, float2 v) { *(float2*)p = v; }

__global__ void k_reset() {
    int t = threadIdx.x;
    if (t < NSTEPS) { g_maxDbits[t] = 0; g_cnt[t] = 0u; }
    for (int k = t; k < 256 * 8; k += blockDim.x) g_done[k] = 0u;
}

// smem rows (stride SP), sized for band <= 8:
// sZt[10] | sHn[8] | sZn[8] | sDb[9] | sQ[8] | sSmb[8] | zhU | zhD = 53 rows
__global__ void __launch_bounds__(1024, 1)
k_persist(const float* __restrict__ precip,
          const float* __restrict__ tma_p,
          const float* __restrict__ tmj_p,
          const float* __restrict__ Ztopo,
          const float* __restrict__ mask,
          float* __restrict__ out) {
    extern __shared__ float sm[];
    float* sZt  = sm;                 // Ztopo rows r0-1 .. r1 (static)
    float* sHn  = sZt + 10 * SP;      // persistent own H band, rows r0..r1-1
    float* sZn  = sHn + 8 * SP;       // z = Zt + H (current), rows r0..r1-1
    float* sDb  = sZn + 8 * SP;       // D band, slot = row-(r0-1), slots 0..band
    float* sQ   = sDb + 9 * SP;       // parked dHdt rows r0..r1-1
    float* sSmb = sQ  + 8 * SP;
    float* zhU  = sSmb + 8 * SP;      // z halo row r0-1
    float* zhD  = zhU + SP;           // z halo row r1
    __shared__ unsigned wred[32];
    __shared__ float sdt[1];

    const int t  = threadIdx.x;
    const int ct = t & 511;
    const int rg = t >> 9;
    const int c0 = ct * 2;
    const int lane = t & 31, wid = t >> 5;
    const int nb = gridDim.x, bid = blockIdx.x;
    const int cl = (c0 == 0) ? 0 : c0 - 1;
    const unsigned FULL = 0xFFFFFFFFu;

    int base = NY / nb, rem = NY % nb;
    const int r0 = bid * base + (bid < rem ? bid : rem);
    const int r1 = r0 + base + (bid < rem ? 1 : 0);
    const int band = r1 - r0;                  // <= 8 (buffers sized for 8)

    const int splitA = (band + 1) >> 1;
    const int a_lo = rg ? splitA : 0;          // own H/dHdt rows (band-local)
    const int a_hi = rg ? band : splitA;
    const int nB = band - 1;
    const int splitB = (nB + 1) >> 1;
    const int bI_lo = rg ? splitB : 0;         // interior D rows
    const int bI_hi = rg ? nB : splitB;

    const float tma = tma_p[0], tmj = tmj_p[0];
    const float CFACT = (float)(1e-17 * 8927.1 * 8927.1 * 8927.1);
    const bool p0in = (ct > 0);
    const bool p1in = (ct < 511);

    // ---- one-time init ----
    if (t < 53) { sm[t * SP + 1024] = 0.f; sm[t * SP + 1025] = 0.f; }
    for (int sl = rg; sl <= band + 1; sl += 2) {
        int row = r0 - 1 + sl;
        float2 zt = make_float2(0.f, 0.f);
        if (row >= 0 && row < NY) zt = ld2(Ztopo + row * NX + c0);
        st2(sZt + sl * SP + c0, zt);
    }
    __syncthreads();
    for (int jb = rg; jb < band; jb += 2) {
        int j = r0 + jb;
        st2(sHn + jb * SP + c0, make_float2(0.f, 0.f));
        float2 zt = ld2(sZt + (jb + 1) * SP + c0);
        st2(sZn + jb * SP + c0, zt);               // z = Zt (H = 0)
        float2 pr = ld2(precip + j * NX + c0);
        float2 mk = ld2(mask + j * NX + c0);
        st2(sSmb + jb * SP + c0,
            make_float2(smb_of(zt.x, pr.x, mk.x, tma, tmj),
                        smb_of(zt.y, pr.y, mk.y, tma, tmj)));
    }
    if (rg == 0) {
        #pragma unroll
        for (int k = 0; k < 9; k++) st2(sDb + k * SP + c0, make_float2(EPS, EPS));
        st2(zhU + c0, ld2(sZt + c0));                   // z(r0-1) at step 0 (H=0)
    } else {
        st2(zhD + c0, ld2(sZt + (band + 1) * SP + c0)); // z(r1) at step 0
    }
    __syncthreads();

    float dt = 0.5f;                 // maxD_0 = EPS -> dt_0 = DTMAX
    float time = 0.0f, tlast = 0.0f;

    // ---- prologue: dHdt_0 (H=0, D=EPS), rolled ----
    {
        float2 zu = (a_lo == 0) ? ld2(zhU + c0) : ld2(sZn + (a_lo - 1) * SP + c0);
        float2 zc = ld2(sZn + a_lo * SP + c0);
        float2 Dup = ld2(sDb + a_lo * SP + c0);
        float Dup_l = sDb[a_lo * SP + cl];
        for (int jb = a_lo; jb < a_hi; jb++) {
            float2 zd = (jb == band - 1) ? ld2(zhD + c0) : ld2(sZn + (jb + 1) * SP + c0);
            float zl = sZn[jb * SP + cl];
            float zr = sZn[jb * SP + c0 + 2];
            float2 Dcu = ld2(sDb + (jb + 1) * SP + c0);
            float Dcu_l = sDb[(jb + 1) * SP + cl];
            float qxr0 = -(0.5f * (Dup.x + Dcu.x)) * (zc.y - zc.x) * INV;
            float qxl0 = -(0.5f * (Dup_l + Dcu_l)) * (zc.x - zl) * INV;
            float qyd0 = -(0.5f * (Dcu_l + Dcu.x)) * (zd.x - zc.x) * INV;
            float qyu0 = -(0.5f * (Dup_l + Dup.x)) * (zc.x - zu.x) * INV;
            float q0 = -((qxr0 - qxl0) * INV + (qyd0 - qyu0) * INV);
            float qxr1 = -(0.5f * (Dup.y + Dcu.y)) * (zr - zc.y) * INV;
            float qxl1 = -(0.5f * (Dup.x + Dcu.x)) * (zc.y - zc.x) * INV;
            float qyd1 = -(0.5f * (Dcu.x + Dcu.y)) * (zd.y - zc.y) * INV;
            float qyu1 = -(0.5f * (Dup.x + Dup.y)) * (zc.y - zu.y) * INV;
            float q1 = -((qxr1 - qxl1) * INV + (qyd1 - qyu1) * INV);
            st2(sQ + jb * SP + c0, make_float2(q0, q1));
            zu = zc; zc = zd; Dup = Dcu; Dup_l = Dcu_l;
        }
    }
    __syncthreads();

    for (int s = 0; s < NSTEPS; s++) {
        float tnew = time + dt;
        bool  upd  = (tnew - tlast) >= 5.0f;
        const bool last = (s == NSTEPS - 1);
        float* HB = ((s + 1) & 1) ? g_H1 : g_H0;   // H_{s+1} boundary buffer

        // ---- A: apply dt_s, stage Hn and Zn ----
        for (int jb = a_lo; jb < a_hi; jb++) {
            int j = r0 + jb;
            float2 h2  = ld2(sHn + jb * SP + c0);
            float2 q2  = ld2(sQ + jb * SP + c0);
            float2 sb2 = ld2(sSmb + jb * SP + c0);
            float2 zt2 = ld2(sZt + (jb + 1) * SP + c0);
            bool jIn = (j > 0) && (j < NY - 1);
            float Hn0 = (jIn && p0in) ? fmaxf(h2.x + dt * (q2.x + sb2.x), 0.f) : h2.x;
            float Hn1 = (jIn && p1in) ? fmaxf(h2.y + dt * (q2.y + sb2.y), 0.f) : h2.y;
            float2 Hn2 = make_float2(Hn0, Hn1);
            float Zn0 = zt2.x + Hn0, Zn1 = zt2.y + Hn1;
            st2(sHn + jb * SP + c0, Hn2);
            st2(sZn + jb * SP + c0, make_float2(Zn0, Zn1));
            if (jb == 0 || jb == band - 1) st2(HB + j * NX + c0, Hn2);
            if (last) st2(out + j * NX + c0, Hn2);
            if (upd) {
                float2 pr = ld2(precip + j * NX + c0);
                float2 mk = ld2(mask + j * NX + c0);
                st2(sSmb + jb * SP + c0,
                    make_float2(smb_of(Zn0, pr.x, mk.x, tma, tmj),
                                smb_of(Zn1, pr.y, mk.y, tma, tmj)));
            }
        }
        time = tnew;
        if (upd) tlast = tnew;
        __syncthreads();
        if (last) break;
        if (t == 0) red_add_rel(&g_done[bid * 8], 1u);     // publish H_{s+1} boundary rows

        // ---- B: D_{s+1} interior (rolled, scalar LDS for right neighbors) ----
        float lmax = 0.f;
        if (bI_lo < bI_hi) {
            float2 ha = ld2(sHn + bI_lo * SP + c0); float haR = sHn[bI_lo * SP + c0 + 2];
            float2 za = ld2(sZn + bI_lo * SP + c0); float zaR = sZn[bI_lo * SP + c0 + 2];
            for (int jb = bI_lo; jb < bI_hi; jb++) {
                float2 hb = ld2(sHn + (jb + 1) * SP + c0); float hbR = sHn[(jb + 1) * SP + c0 + 2];
                float2 zb = ld2(sZn + (jb + 1) * SP + c0); float zbR = sZn[(jb + 1) * SP + c0 + 2];
                float D0 = dcalc(ha.x, ha.y, hb.x, hb.y, za.x, za.y, zb.x, zb.y, CFACT);
                float D1 = dcalc(ha.y, haR, hb.y, hbR, za.y, zaR, zb.y, zbR, CFACT);
                st2(sDb + (jb + 1) * SP + c0, make_float2(D0, D1));
                lmax = fmaxf(lmax, D0);
                if (p1in) lmax = fmaxf(lmax, D1);
                ha = hb; haR = hbR; za = zb; zaR = zbR;
            }
        }

        // wait neighbor H_{s+1} flags
        if (t == 0 && bid > 0)       { while (ld_acq(&g_done[(bid - 1) * 8]) < (unsigned)(s + 1)) __nanosleep(20); }
        if (t == 32 && bid < nb - 1) { while (ld_acq(&g_done[(bid + 1) * 8]) < (unsigned)(s + 1)) __nanosleep(20); }
        __syncthreads();

        // ---- boundary D rows + z halo staging ----
        if (rg == 0) {
            if (r0 >= 1) {
                const float* pa = HB + (r0 - 1) * NX + c0;
                float2 ha = __ldcg((const float2*)pa);
                float  haR = p1in ? __ldcg(pa + 2) : 0.f;
                float2 zta = ld2(sZt + c0); float ztaR = sZt[c0 + 2];
                float2 za = make_float2(zta.x + ha.x, zta.y + ha.y); float zaR = ztaR + haR;
                st2(zhU + c0, za);
                float2 hb = ld2(sHn + c0); float hbR = sHn[c0 + 2];
                float2 zb = ld2(sZn + c0); float zbR = sZn[c0 + 2];
                float D0 = dcalc(ha.x, ha.y, hb.x, hb.y, za.x, za.y, zb.x, zb.y, CFACT);
                float D1 = dcalc(ha.y, haR, hb.y, hbR, za.y, zaR, zb.y, zbR, CFACT);
                st2(sDb + c0, make_float2(D0, D1));
                lmax = fmaxf(lmax, D0);
                if (p1in) lmax = fmaxf(lmax, D1);
            }
        } else {
            if (r1 <= NY - 1) {
                float2 ha = ld2(sHn + (band - 1) * SP + c0); float haR = sHn[(band - 1) * SP + c0 + 2];
                float2 za = ld2(sZn + (band - 1) * SP + c0); float zaR = sZn[(band - 1) * SP + c0 + 2];
                const float* pb = HB + r1 * NX + c0;
                float2 hb = __ldcg((const float2*)pb);
                float  hbR = p1in ? __ldcg(pb + 2) : 0.f;
                float2 ztb = ld2(sZt + (band + 1) * SP + c0); float ztbR = sZt[(band + 1) * SP + c0 + 2];
                float2 zb = make_float2(ztb.x + hb.x, ztb.y + hb.y); float zbR = ztbR + hbR;
                st2(zhD + c0, zb);
                float D0 = dcalc(ha.x, ha.y, hb.x, hb.y, za.x, za.y, zb.x, zb.y, CFACT);
                float D1 = dcalc(ha.y, haR, hb.y, hbR, za.y, zaR, zb.y, zbR, CFACT);
                st2(sDb + band * SP + c0, make_float2(D0, D1));
                lmax = fmaxf(lmax, D0);
                if (p1in) lmax = fmaxf(lmax, D1);
            }
        }

        // ---- block max -> atomicMax slot s+1 + arrive counter (early) ----
        unsigned lb = __reduce_max_sync(FULL, __float_as_uint(lmax));
        if (lane == 0) wred[wid] = lb;
        __syncthreads();
        if (wid == 0) {
            unsigned m = __reduce_max_sync(FULL, wred[lane]);
            if (lane == 0) {
                atomicMax(&g_maxDbits[s + 1], (int)m);
                red_add_rel(&g_cnt[s + 1], 1u);
            }
        }

        // ---- C: dHdt_{s+1} (rolled, scalar LDS laterals) — overlaps max propagation ----
        {
            float2 zu = (a_lo == 0) ? ld2(zhU + c0) : ld2(sZn + (a_lo - 1) * SP + c0);
            float2 zc = ld2(sZn + a_lo * SP + c0);
            float2 Dup = ld2(sDb + a_lo * SP + c0);
            float Dup_l = sDb[a_lo * SP + cl];
            for (int jb = a_lo; jb < a_hi; jb++) {
                float2 zd = (jb == band - 1) ? ld2(zhD + c0) : ld2(sZn + (jb + 1) * SP + c0);
                float zl = sZn[jb * SP + cl];
                float zr = sZn[jb * SP + c0 + 2];
                float2 Dcu = ld2(sDb + (jb + 1) * SP + c0);
                float Dcu_l = sDb[(jb + 1) * SP + cl];
                float qxr0 = -(0.5f * (Dup.x + Dcu.x)) * (zc.y - zc.x) * INV;
                float qxl0 = -(0.5f * (Dup_l + Dcu_l)) * (zc.x - zl) * INV;
                float qyd0 = -(0.5f * (Dcu_l + Dcu.x)) * (zd.x - zc.x) * INV;
                float qyu0 = -(0.5f * (Dup_l + Dup.x)) * (zc.x - zu.x) * INV;
                float q0 = -((qxr0 - qxl0) * INV + (qyd0 - qyu0) * INV);
                float qxr1 = -(0.5f * (Dup.y + Dcu.y)) * (zr - zc.y) * INV;
                float qxl1 = -(0.5f * (Dup.x + Dcu.x)) * (zc.y - zc.x) * INV;
                float qyd1 = -(0.5f * (Dcu.x + Dcu.y)) * (zd.y - zc.y) * INV;
                float qyu1 = -(0.5f * (Dup.x + Dup.y)) * (zc.y - zu.y) * INV;
                float q1 = -((qxr1 - qxl1) * INV + (qyd1 - qyu1) * INV);
                st2(sQ + jb * SP + c0, make_float2(q0, q1));
                zu = zc; zc = zd; Dup = Dcu; Dup_l = Dcu_l;
            }
        }
        __syncthreads();

        // ---- D: fetch dt_{s+1} ----
        if (t == 0) {
            while (ld_acq(&g_cnt[s + 1]) < (unsigned)nb) __nanosleep(20);
            sdt[0] = __int_as_float(__ldcg(&g_maxDbits[s + 1]));
        }
        __syncthreads();
        float maxD = sdt[0];
        dt = fminf(2500.0f / (2.7f * maxD), 0.5f);
        if (!(time < 32.0f)) dt = 0.0f;
    }
}

extern "C" void kernel_launch(void* const* d_in, const int* in_sizes, int n_in,
                              void* d_out, int out_size) {
    const float* precip = (const float*)d_in[0];
    const float* tma_p  = (const float*)d_in[1];
    const float* tmj_p  = (const float*)d_in[2];
    const float* Ztopo  = (const float*)d_in[3];
    const float* mask   = (const float*)d_in[4];
    float* out = (float*)d_out;

    int dev = 0;
    cudaGetDevice(&dev);
    int sms = 0;
    cudaDeviceGetAttribute(&sms, cudaDevAttrMultiProcessorCount, dev);
    if (sms < 1) sms = 1;
    if (sms > 256) sms = 256;
    if (sms < 128) sms = 128;   // keep band <= 8 (smem sized for 8)

    const int smem_bytes = 53 * SP * (int)sizeof(float);
    cudaFuncSetAttribute(k_persist, cudaFuncAttributeMaxDynamicSharedMemorySize, smem_bytes);

    k_reset<<<1, 1024>>>();
    k_persist<<<sms, 1024, smem_bytes>>>(precip, tma_p, tmj_p, Ztopo, mask, out);
}